// round 16
// baseline (speedup 1.0000x reference)
#include <cuda_runtime.h>
#include <cuda_fp16.h>

#define C_ 192
#define NH_ 8
#define HD_ 24
#define CEXP_ 0.29448618f  // (HD^-0.5) * log2(e)

// ---- smem float-index offsets (low region: 8192 bytes) ----
#define BIASf 0      // 392 floats: b_qkv[384] | bveff[8]
#define BIAS2f 392   // 196 u32: f16x2 bias pairs (q pairs pre-scaled by CEXP)
#define GAMMAf 588
#define BETAf 780
#define VWf 972      // [8][68] fp32
#define OUTPf 1516   // [8][64] fp32
// ---- byte offsets ----
// stage fp32 [192][68] = 52224 B at byte 8192
// f16 A tile [64][400B] = 25600 B OVERLAID at byte 8192 (after stage read)
// B double-buffer 2 x 12800 B OVERLAID at byte 33792 (dead stage space)
#define OFF_ASH 8192
#define OFF_BBUF 33792
#define CHUNKB 12800
#define STAGEf 2048
#define SMEM_BYTES 60416

__device__ float g_bveff[NH_];
__device__ float g_bpmean;
// [12 kt][400 n][32B]; within 32B, k order: [0,1,8,9][2,3,10,11][4,5,12,13][6,7,14,15]
__device__ uint4 g_wpackB[9600];

// ---------------- asm helpers ----------------
__device__ __forceinline__ unsigned smem_u32(const void* p) {
  unsigned a;
  asm("{ .reg .u64 t; cvta.to.shared.u64 t, %1; cvt.u32.u64 %0, t; }"
      : "=r"(a) : "l"(p));
  return a;
}
__device__ __forceinline__ void cpasync16(unsigned dst, const void* src) {
  asm volatile("cp.async.cg.shared.global [%0], [%1], 16;" :: "r"(dst),
               "l"(src));
}
#define CP_COMMIT() asm volatile("cp.async.commit_group;" ::: "memory")
#define CP_WAIT0() asm volatile("cp.async.wait_group 0;" ::: "memory")

__device__ __forceinline__ void ldsm4(unsigned* r, unsigned addr) {
  asm volatile("ldmatrix.sync.aligned.m8n8.x4.shared.b16 {%0,%1,%2,%3}, [%4];"
               : "=r"(r[0]), "=r"(r[1]), "=r"(r[2]), "=r"(r[3]) : "r"(addr));
}
__device__ __forceinline__ void mma_h(unsigned* c, unsigned a0, unsigned a1,
                                      unsigned a2, unsigned a3, unsigned b0,
                                      unsigned b1) {
  asm volatile(
      "mma.sync.aligned.m16n8k16.row.col.f16.f16.f16.f16 "
      "{%0,%1},{%2,%3,%4,%5},{%6,%7},{%0,%1};"
      : "+r"(c[0]), "+r"(c[1])
      : "r"(a0), "r"(a1), "r"(a2), "r"(a3), "r"(b0), "r"(b1));
}
__device__ __forceinline__ void mma8h(unsigned* c, unsigned a0, unsigned a1,
                                      unsigned b0) {
  asm volatile(
      "mma.sync.aligned.m16n8k8.row.col.f16.f16.f16.f16 "
      "{%0,%1},{%2,%3},{%4},{%0,%1};"
      : "+r"(c[0]), "+r"(c[1])
      : "r"(a0), "r"(a1), "r"(b0));
}
__device__ __forceinline__ unsigned h2exp2u(unsigned x) {
  unsigned r;
  asm("ex2.approx.f16x2 %0, %1;" : "=r"(r) : "r"(x));
  return r;
}
__device__ __forceinline__ unsigned pack_h2(float hi, float lo) {
  unsigned r;
  asm("cvt.rn.f16x2.f32 %0, %1, %2;" : "=r"(r) : "f"(hi), "f"(lo));
  return r;
}

// ---------------- fused precompute: ONE launch ----------------
// grid = 300 blocks x 256 threads; idx covers 12*400*16 = 76800 pack items.
// Only blocks touching n>=384 (b%25==24) and block 0 need wps.
__global__ void pk_all(const float* __restrict__ w_qkv,
                       const float* __restrict__ b_qkv,
                       const float* __restrict__ w_proj,
                       const float* __restrict__ b_proj) {
  __shared__ float wps[C_];
  const int tid = threadIdx.x;
  const bool need_wps = (blockIdx.x == 0) || (blockIdx.x % 25 == 24);
  if (need_wps) {
    const int wr = tid >> 5, ln = tid & 31;
    #pragma unroll
    for (int rr = 0; rr < 24; ++rr) {
      int row = wr * 24 + rr;
      float s = 0.f;
      #pragma unroll
      for (int c6 = 0; c6 < 6; ++c6) s += w_proj[row * C_ + ln + c6 * 32];
      #pragma unroll
      for (int o = 16; o > 0; o >>= 1) s += __shfl_xor_sync(0xffffffffu, s, o);
      if (ln == 0) wps[row] = s * (1.f / C_);
    }
    __syncthreads();
  }

  const int idx = blockIdx.x * 256 + tid;
  const int k = idx & 15;
  const int n = (idx >> 4) % 400;
  const int kt = idx / 6400;
  float v = 0.f;
  const int kf = kt * 16 + k;
  if (n < 384) {
    v = w_qkv[kf * 576 + n];
  } else if (n < 392) {
    const int h = n - 384;
    float a = 0.f;
    #pragma unroll
    for (int d = 0; d < HD_; ++d)
      a += w_qkv[kf * 576 + 384 + h * HD_ + d] * wps[h * HD_ + d];
    v = a;
  }
  const int byte = kt * 12800 + n * 32 + (((k & 7) >> 1) << 3) +
                   (((k >> 3) & 1) << 2) + ((k & 1) << 1);
  *reinterpret_cast<__half*>(reinterpret_cast<char*>(g_wpackB) + byte) =
      __float2half(v);

  if (blockIdx.x == 0) {
    if (tid < NH_) {
      float a = 0.f;
      #pragma unroll
      for (int d = 0; d < HD_; ++d)
        a += b_qkv[384 + tid * HD_ + d] * wps[tid * HD_ + d];
      g_bveff[tid] = a;
    } else if (tid == NH_) {
      float a = 0.f;
      for (int c = 0; c < C_; ++c) a += b_proj[c];
      g_bpmean = a * (1.f / C_);
    }
  }
}

// ---------------- main fused kernel: 1 window / CTA, 256 threads ----------
__global__ __launch_bounds__(256, 3) void swin_reg_kernel(
    const float* __restrict__ x, const float* __restrict__ gamma,
    const float* __restrict__ beta, const float* __restrict__ b_qkv,
    float* __restrict__ out) {
  extern __shared__ unsigned char smraw[];
  float* smf = reinterpret_cast<float*>(smraw);
  unsigned* smu = reinterpret_cast<unsigned*>(smraw);
  const unsigned sbase = smem_u32(smraw);
  const int tid = threadIdx.x;
  const int h = tid >> 5;  // warp = head
  const int lane = tid & 31;
  const int g = lane >> 2;
  const int t = lane & 3;

  const int win = blockIdx.x;
  const int bN = win >> 10;
  const int wy = (win >> 5) & 31;
  const int wx = win & 31;
  const float* xb = x + (size_t)bN * (C_ * 65536) + wy * 2048 + wx * 8;

  // ---- stage x via cp.async ----
  #pragma unroll
  for (int u = 0; u < 12; ++u) {
    int idx = tid + u * 256;
    int c = idx >> 4;
    int rem = idx & 15;
    int ty = rem >> 1, t4 = rem & 1;
    cpasync16(sbase + (STAGEf + c * 68 + ty * 8 + t4 * 4) * 4,
              xb + (size_t)c * 65536 + ty * 256 + t4 * 4);
  }
  CP_COMMIT();

  for (int i = tid; i < 392; i += 256)
    smf[BIASf + i] = (i < 384) ? b_qkv[i] : g_bveff[i - 384];
  if (tid < C_) {
    smf[GAMMAf + tid] = gamma[tid];
    smf[BETAf + tid] = beta[tid];
  }
  CP_WAIT0();
  __syncthreads();

  // bias f16x2 pairs; q-col pairs (tid<96) pre-scaled by CEXP
  if (tid < 196) {
    float s = (tid < 96) ? CEXP_ : 1.f;
    smu[BIAS2f + tid] =
        pack_h2(smf[BIASf + 2 * tid + 1] * s, smf[BIASf + 2 * tid] * s);
  }

  // ---- LayerNorm (2-phase: read+reduce, sync, write A over stage) ----
  {
    int tok = tid >> 2, cl2 = tid & 3;
    float v0a[24], v1a[24];
    float sum = 0.f, sq = 0.f;
    #pragma unroll
    for (int i = 0; i < 24; ++i) {
      int c = 8 * i + 2 * cl2;
      float v0 = smf[STAGEf + c * 68 + tok];
      float v1 = smf[STAGEf + (c + 1) * 68 + tok];
      v0a[i] = v0;
      v1a[i] = v1;
      sum += v0 + v1;
      sq += v0 * v0 + v1 * v1;
    }
    sum += __shfl_xor_sync(0xffffffffu, sum, 1);
    sq += __shfl_xor_sync(0xffffffffu, sq, 1);
    sum += __shfl_xor_sync(0xffffffffu, sum, 2);
    sq += __shfl_xor_sync(0xffffffffu, sq, 2);
    float mu = sum * (1.f / C_);
    float rstd = rsqrtf(sq * (1.f / C_) - mu * mu + 1e-5f);
    __syncthreads();  // ALL stage reads done; upper stage space now reusable

    // prefetch B chunk 0 into dead stage space (overlaps LN write phase)
    {
      const uint4* src = g_wpackB;
      #pragma unroll
      for (int i = 0; i < 4; ++i) {
        int ii = tid + i * 256;
        if (ii < 800) cpasync16(sbase + OFF_BBUF + ii * 16, src + ii);
      }
      CP_COMMIT();
    }

    #pragma unroll
    for (int i = 0; i < 24; ++i) {
      int c = 8 * i + 2 * cl2;
      float xn0 = (v0a[i] - mu) * rstd * smf[GAMMAf + c] + smf[BETAf + c];
      float xn1 =
          (v1a[i] - mu) * rstd * smf[GAMMAf + c + 1] + smf[BETAf + c + 1];
      *reinterpret_cast<unsigned*>(smraw + OFF_ASH + tok * 400 + c * 2) =
          pack_h2(xn1, xn0);
    }
  }

  // ---- per-head GEMM: A from smem (ldsm), B from smem double-buffer ----
  unsigned accq[4][3][2], acck[4][3][2], accv[2];
  #pragma unroll
  for (int mi = 0; mi < 4; ++mi)
    #pragma unroll
    for (int j = 0; j < 3; ++j) {
      accq[mi][j][0] = accq[mi][j][1] = 0u;
      acck[mi][j][0] = acck[mi][j][1] = 0u;
    }
  accv[0] = accv[1] = 0u;
  {
    const int arow = (lane & 7) + ((lane >> 3) & 1) * 8;
    const int akoff = (lane >> 4) * 16;
    const unsigned aBase = sbase + OFF_ASH + arow * 400 + akoff;

    unsigned boff[7];
    #pragma unroll
    for (int j = 0; j < 7; ++j) {
      int ntg = (j < 3) ? (3 * h + j) : ((j < 6) ? (24 + 3 * h + j - 3) : 48);
      boff[j] = (unsigned)((ntg * 8 + g) * 32 + t * 8);
    }

    #pragma unroll
    for (int kt = 0; kt < 12; ++kt) {
      CP_WAIT0();
      __syncthreads();  // chunk kt ready; all warps past kt-1 (buffer reuse)
      if (kt < 11) {
        const uint4* src = g_wpackB + (kt + 1) * 800;
        const unsigned db = sbase + OFF_BBUF + ((kt + 1) & 1) * CHUNKB;
        #pragma unroll
        for (int i = 0; i < 4; ++i) {
          int ii = tid + i * 256;
          if (ii < 800) cpasync16(db + ii * 16, src + ii);
        }
        CP_COMMIT();
      }
      const unsigned char* bb = smraw + OFF_BBUF + (kt & 1) * CHUNKB;
      uint2 Bc[7];
      #pragma unroll
      for (int j = 0; j < 6; ++j)
        Bc[j] = *reinterpret_cast<const uint2*>(bb + boff[j]);
      if (h < 4) Bc[6] = *reinterpret_cast<const uint2*>(bb + boff[6]);
      #pragma unroll
      for (int mi = 0; mi < 4; ++mi) {
        unsigned Af[4];
        ldsm4(Af, aBase + mi * 6400 + kt * 32);
        #pragma unroll
        for (int j = 0; j < 3; ++j)
          mma_h(accq[mi][j], Af[0], Af[1], Af[2], Af[3], Bc[j].x, Bc[j].y);
        #pragma unroll
        for (int j = 0; j < 3; ++j)
          mma_h(acck[mi][j], Af[0], Af[1], Af[2], Af[3], Bc[3 + j].x,
                Bc[3 + j].y);
        if (h == mi)
          mma_h(accv, Af[0], Af[1], Af[2], Af[3], Bc[6].x, Bc[6].y);
      }
    }
  }

  // ---- q: (q+bq)*CEXP via HFMA2 (bias pre-scaled); k: plain bias add ----
  {
    const __half2 ce2 = __float2half2_rn(CEXP_);
    #pragma unroll
    for (int j = 0; j < 3; ++j) {
      __half2 bq =
          *reinterpret_cast<__half2*>(smu + BIAS2f + (3 * h + j) * 4 + t);
      __half2 bk =
          *reinterpret_cast<__half2*>(smu + BIAS2f + 96 + (3 * h + j) * 4 + t);
      #pragma unroll
      for (int mi = 0; mi < 4; ++mi) {
        #pragma unroll
        for (int c = 0; c < 2; ++c) {
          __half2 q2 =
              __hfma2(*reinterpret_cast<__half2*>(&accq[mi][j][c]), ce2, bq);
          accq[mi][j][c] = *reinterpret_cast<unsigned*>(&q2);
          __half2 k2 =
              __hadd2(*reinterpret_cast<__half2*>(&acck[mi][j][c]), bk);
          acck[mi][j][c] = *reinterpret_cast<unsigned*>(&k2);
        }
      }
    }
  }

  // ---- vw: warp h<4 writes all 8 head-cols for rows [h*16, h*16+16) ----
  if (h < 4) {
    __half2 c0 = *reinterpret_cast<__half2*>(&accv[0]);  // row g
    __half2 c1 = *reinterpret_cast<__half2*>(&accv[1]);  // row g+8
    int col0 = 2 * t, col1 = 2 * t + 1;
    float b0 = smf[BIASf + 384 + col0], b1 = smf[BIASf + 384 + col1];
    smf[VWf + col0 * 68 + h * 16 + g] = __low2float(c0) + b0;
    smf[VWf + col1 * 68 + h * 16 + g] = __high2float(c0) + b1;
    smf[VWf + col0 * 68 + h * 16 + 8 + g] = __low2float(c1) + b0;
    smf[VWf + col1 * 68 + h * 16 + 8 + g] = __high2float(c1) + b1;
  }
  __syncthreads();

  // preload vw pairs as f16x2 (one per kb)
  __half2 vv2[8];
  #pragma unroll
  for (int kb = 0; kb < 8; ++kb) {
    float2 vvk =
        *reinterpret_cast<const float2*>(smf + VWf + h * 68 + kb * 8 + t * 2);
    vv2[kb] = __floats2half2_rn(vvk.x, vvk.y);
  }

  // ---- attention: f16-acc logits (pre-scaled), f16x2 no-max softmax ----
  #pragma unroll
  for (int mt2 = 0; mt2 < 4; ++mt2) {
    unsigned acc[8][2];
    #pragma unroll
    for (int kb = 0; kb < 8; ++kb) acc[kb][0] = acc[kb][1] = 0u;
    #pragma unroll
    for (int kb = 0; kb < 8; ++kb) {
      mma_h(acc[kb], accq[mt2][0][0], accq[mt2][0][1], accq[mt2][1][0],
            accq[mt2][1][1], acck[kb >> 1][0][kb & 1],
            acck[kb >> 1][1][kb & 1]);
      mma8h(acc[kb], accq[mt2][2][0], accq[mt2][2][1],
            acck[kb >> 1][2][kb & 1]);
    }
    // row g -> acc[.][0], row g+8 -> acc[.][1]; halves = same-row columns
    __half2 sp2a = __float2half2_rn(0.f), sp2b = sp2a;
    __half2 sv2a = sp2a, sv2b = sp2a;
    #pragma unroll
    for (int kb = 0; kb < 8; ++kb) {
      unsigned p0u = h2exp2u(acc[kb][0]);
      unsigned p1u = h2exp2u(acc[kb][1]);
      __half2 p0 = *reinterpret_cast<__half2*>(&p0u);
      __half2 p1 = *reinterpret_cast<__half2*>(&p1u);
      sp2a = __hadd2(sp2a, p0);
      sp2b = __hadd2(sp2b, p1);
      sv2a = __hfma2(p0, vv2[kb], sv2a);
      sv2b = __hfma2(p1, vv2[kb], sv2b);
    }
    float2 fpa = __half22float2(sp2a), fpb = __half22float2(sp2b);
    float2 fva = __half22float2(sv2a), fvb = __half22float2(sv2b);
    float sp0 = fpa.x + fpa.y, sp1 = fpb.x + fpb.y;
    float sv0 = fva.x + fva.y, sv1 = fvb.x + fvb.y;
    sp0 += __shfl_xor_sync(0xffffffffu, sp0, 1);
    sv0 += __shfl_xor_sync(0xffffffffu, sv0, 1);
    sp1 += __shfl_xor_sync(0xffffffffu, sp1, 1);
    sv1 += __shfl_xor_sync(0xffffffffu, sv1, 1);
    sp0 += __shfl_xor_sync(0xffffffffu, sp0, 2);
    sv0 += __shfl_xor_sync(0xffffffffu, sv0, 2);
    sp1 += __shfl_xor_sync(0xffffffffu, sp1, 2);
    sv1 += __shfl_xor_sync(0xffffffffu, sv1, 2);
    if (t == 0) {
      smf[OUTPf + h * 64 + mt2 * 16 + g] = __fdividef(sv0, sp0);
      smf[OUTPf + h * 64 + mt2 * 16 + g + 8] = __fdividef(sv1, sp1);
    }
  }
  __syncthreads();

  // ---- final: sum 8 heads, sigmoid, store
  if (tid < 64) {
    float s = 0.f;
    #pragma unroll
    for (int hh = 0; hh < 8; ++hh) s += smf[OUTPf + hh * 64 + tid];
    float v = s + g_bpmean;
    float sig = 1.f / (1.f + __expf(-v));
    out[(size_t)bN * 65536 + (wy * 8 + (tid >> 3)) * 256 + wx * 8 +
        (tid & 7)] = sig;
  }
}

extern "C" void kernel_launch(void* const* d_in, const int* in_sizes, int n_in,
                              void* d_out, int out_size) {
  const float* x = (const float*)d_in[0];
  const float* gamma = (const float*)d_in[1];
  const float* beta = (const float*)d_in[2];
  const float* w_qkv = (const float*)d_in[3];
  const float* b_qkv = (const float*)d_in[4];
  const float* w_proj = (const float*)d_in[5];
  const float* b_proj = (const float*)d_in[6];
  float* out = (float*)d_out;

  cudaFuncSetAttribute(swin_reg_kernel,
                       cudaFuncAttributeMaxDynamicSharedMemorySize, SMEM_BYTES);

  pk_all<<<300, 256>>>(w_qkv, b_qkv, w_proj, b_proj);
  swin_reg_kernel<<<8192, 256, SMEM_BYTES>>>(x, gamma, beta, b_qkv, out);
}

// round 17
// speedup vs baseline: 1.0979x; 1.0979x over previous
#include <cuda_runtime.h>
#include <cuda_fp16.h>

#define C_ 192
#define NH_ 8
#define HD_ 24
#define CEXP_ 0.29448618f  // (HD^-0.5) * log2(e)

// ---- smem float-index offsets (low region: 8192 bytes) ----
#define BIASf 0      // 392 floats: b_qkv[384] | bveff[8]
#define BIAS2f 392   // 196 u32: f16x2 bias pairs (q pairs pre-scaled by CEXP)
#define GAMMAf 588
#define BETAf 780
#define VWf 972      // [8][68] fp32
#define OUTPf 1516   // [8][64] fp32
// ---- byte offsets ----
// stage fp32 [192][68] = 52224 B at byte 8192
// f16 A tile [64][400B] = 25600 B OVERLAID at byte 8192 (after stage read)
#define OFF_ASH 8192
#define STAGEf 2048
#define SMEM_BYTES 60416

__device__ float g_bveff[NH_];
__device__ float g_bpmean;
// [12 kt][400 n][32B]; within 32B, k order: [0,1,8,9][2,3,10,11][4,5,12,13][6,7,14,15]
__device__ uint4 g_wpackB[9600];

// ---------------- asm helpers ----------------
__device__ __forceinline__ unsigned smem_u32(const void* p) {
  unsigned a;
  asm("{ .reg .u64 t; cvta.to.shared.u64 t, %1; cvt.u32.u64 %0, t; }"
      : "=r"(a) : "l"(p));
  return a;
}
__device__ __forceinline__ void cpasync16(unsigned dst, const void* src) {
  asm volatile("cp.async.cg.shared.global [%0], [%1], 16;" :: "r"(dst),
               "l"(src));
}
#define CP_COMMIT() asm volatile("cp.async.commit_group;" ::: "memory")
#define CP_WAIT0() asm volatile("cp.async.wait_group 0;" ::: "memory")

__device__ __forceinline__ void ldsm4(unsigned* r, unsigned addr) {
  asm volatile("ldmatrix.sync.aligned.m8n8.x4.shared.b16 {%0,%1,%2,%3}, [%4];"
               : "=r"(r[0]), "=r"(r[1]), "=r"(r[2]), "=r"(r[3]) : "r"(addr));
}
__device__ __forceinline__ void mma_h(unsigned* c, unsigned a0, unsigned a1,
                                      unsigned a2, unsigned a3, unsigned b0,
                                      unsigned b1) {
  asm volatile(
      "mma.sync.aligned.m16n8k16.row.col.f16.f16.f16.f16 "
      "{%0,%1},{%2,%3,%4,%5},{%6,%7},{%0,%1};"
      : "+r"(c[0]), "+r"(c[1])
      : "r"(a0), "r"(a1), "r"(a2), "r"(a3), "r"(b0), "r"(b1));
}
__device__ __forceinline__ void mma8h(unsigned* c, unsigned a0, unsigned a1,
                                      unsigned b0) {
  asm volatile(
      "mma.sync.aligned.m16n8k8.row.col.f16.f16.f16.f16 "
      "{%0,%1},{%2,%3},{%4},{%0,%1};"
      : "+r"(c[0]), "+r"(c[1])
      : "r"(a0), "r"(a1), "r"(b0));
}
__device__ __forceinline__ unsigned h2exp2u(unsigned x) {
  unsigned r;
  asm("ex2.approx.f16x2 %0, %1;" : "=r"(r) : "r"(x));
  return r;
}
__device__ __forceinline__ float ex2a(float x) {
  float r;
  asm("ex2.approx.f32 %0, %1;" : "=f"(r) : "f"(x));
  return r;
}
__device__ __forceinline__ unsigned pack_h2(float hi, float lo) {
  unsigned r;
  asm("cvt.rn.f16x2.f32 %0, %1, %2;" : "=r"(r) : "f"(hi), "f"(lo));
  return r;
}

// ---------------- fused precompute: ONE launch ----------------
// grid = 300 blocks x 256 threads; idx covers 12*400*16 = 76800 pack items.
// Only blocks touching n>=384 (b%25==24) and block 0 need wps.
__global__ void pk_all(const float* __restrict__ w_qkv,
                       const float* __restrict__ b_qkv,
                       const float* __restrict__ w_proj,
                       const float* __restrict__ b_proj) {
  __shared__ float wps[C_];
  const int tid = threadIdx.x;
  const bool need_wps = (blockIdx.x == 0) || (blockIdx.x % 25 == 24);
  if (need_wps) {
    const int wr = tid >> 5, ln = tid & 31;
    #pragma unroll
    for (int rr = 0; rr < 24; ++rr) {
      int row = wr * 24 + rr;
      float s = 0.f;
      #pragma unroll
      for (int c6 = 0; c6 < 6; ++c6) s += w_proj[row * C_ + ln + c6 * 32];
      #pragma unroll
      for (int o = 16; o > 0; o >>= 1) s += __shfl_xor_sync(0xffffffffu, s, o);
      if (ln == 0) wps[row] = s * (1.f / C_);
    }
    __syncthreads();
  }

  const int idx = blockIdx.x * 256 + tid;
  const int k = idx & 15;
  const int n = (idx >> 4) % 400;
  const int kt = idx / 6400;
  float v = 0.f;
  const int kf = kt * 16 + k;
  if (n < 384) {
    v = w_qkv[kf * 576 + n];
  } else if (n < 392) {
    const int h = n - 384;
    float a = 0.f;
    #pragma unroll
    for (int d = 0; d < HD_; ++d)
      a += w_qkv[kf * 576 + 384 + h * HD_ + d] * wps[h * HD_ + d];
    v = a;
  }
  const int byte = kt * 12800 + n * 32 + (((k & 7) >> 1) << 3) +
                   (((k >> 3) & 1) << 2) + ((k & 1) << 1);
  *reinterpret_cast<__half*>(reinterpret_cast<char*>(g_wpackB) + byte) =
      __float2half(v);

  if (blockIdx.x == 0) {
    if (tid < NH_) {
      float a = 0.f;
      #pragma unroll
      for (int d = 0; d < HD_; ++d)
        a += b_qkv[384 + tid * HD_ + d] * wps[tid * HD_ + d];
      g_bveff[tid] = a;
    } else if (tid == NH_) {
      float a = 0.f;
      for (int c = 0; c < C_; ++c) a += b_proj[c];
      g_bpmean = a * (1.f / C_);
    }
  }
}

// ---------------- main fused kernel: 1 window / CTA, 256 threads ----------
__global__ __launch_bounds__(256, 3) void swin_reg_kernel(
    const float* __restrict__ x, const float* __restrict__ gamma,
    const float* __restrict__ beta, const float* __restrict__ b_qkv,
    float* __restrict__ out) {
  extern __shared__ unsigned char smraw[];
  float* smf = reinterpret_cast<float*>(smraw);
  unsigned* smu = reinterpret_cast<unsigned*>(smraw);
  const unsigned sbase = smem_u32(smraw);
  const int tid = threadIdx.x;
  const int h = tid >> 5;  // warp = head
  const int lane = tid & 31;
  const int g = lane >> 2;
  const int t = lane & 3;

  const int win = blockIdx.x;
  const int bN = win >> 10;
  const int wy = (win >> 5) & 31;
  const int wx = win & 31;
  const float* xb = x + (size_t)bN * (C_ * 65536) + wy * 2048 + wx * 8;

  // ---- stage x via cp.async ----
  #pragma unroll
  for (int u = 0; u < 12; ++u) {
    int idx = tid + u * 256;
    int c = idx >> 4;
    int rem = idx & 15;
    int ty = rem >> 1, t4 = rem & 1;
    cpasync16(sbase + (STAGEf + c * 68 + ty * 8 + t4 * 4) * 4,
              xb + (size_t)c * 65536 + ty * 256 + t4 * 4);
  }
  CP_COMMIT();

  for (int i = tid; i < 392; i += 256)
    smf[BIASf + i] = (i < 384) ? b_qkv[i] : g_bveff[i - 384];
  if (tid < C_) {
    smf[GAMMAf + tid] = gamma[tid];
    smf[BETAf + tid] = beta[tid];
  }
  CP_WAIT0();
  __syncthreads();

  // bias f16x2 pairs; q-col pairs (tid<96) pre-scaled by CEXP
  if (tid < 196) {
    float s = (tid < 96) ? CEXP_ : 1.f;
    smu[BIAS2f + tid] =
        pack_h2(smf[BIASf + 2 * tid + 1] * s, smf[BIASf + 2 * tid] * s);
  }

  // ---- LayerNorm (2-phase: read+reduce, sync, write A over stage) ----
  {
    int tok = tid >> 2, cl2 = tid & 3;
    float v0a[24], v1a[24];
    float sum = 0.f, sq = 0.f;
    #pragma unroll
    for (int i = 0; i < 24; ++i) {
      int c = 8 * i + 2 * cl2;
      float v0 = smf[STAGEf + c * 68 + tok];
      float v1 = smf[STAGEf + (c + 1) * 68 + tok];
      v0a[i] = v0;
      v1a[i] = v1;
      sum += v0 + v1;
      sq += v0 * v0 + v1 * v1;
    }
    sum += __shfl_xor_sync(0xffffffffu, sum, 1);
    sq += __shfl_xor_sync(0xffffffffu, sq, 1);
    sum += __shfl_xor_sync(0xffffffffu, sum, 2);
    sq += __shfl_xor_sync(0xffffffffu, sq, 2);
    float mu = sum * (1.f / C_);
    float rstd = rsqrtf(sq * (1.f / C_) - mu * mu + 1e-5f);
    __syncthreads();  // all stage reads done before A overlay writes
    #pragma unroll
    for (int i = 0; i < 24; ++i) {
      int c = 8 * i + 2 * cl2;
      float xn0 = (v0a[i] - mu) * rstd * smf[GAMMAf + c] + smf[BETAf + c];
      float xn1 =
          (v1a[i] - mu) * rstd * smf[GAMMAf + c + 1] + smf[BETAf + c + 1];
      *reinterpret_cast<unsigned*>(smraw + OFF_ASH + tok * 400 + c * 2) =
          pack_h2(xn1, xn0);
    }
  }
  __syncthreads();

  // ---- per-head GEMM, register accumulators, JIT B loads (imm offsets) ----
  unsigned accq[4][3][2], acck[4][3][2], accv[2];
  #pragma unroll
  for (int mi = 0; mi < 4; ++mi)
    #pragma unroll
    for (int j = 0; j < 3; ++j) {
      accq[mi][j][0] = accq[mi][j][1] = 0u;
      acck[mi][j][0] = acck[mi][j][1] = 0u;
    }
  accv[0] = accv[1] = 0u;
  {
    const int arow = (lane & 7) + ((lane >> 3) & 1) * 8;
    const int akoff = (lane >> 4) * 16;
    const unsigned aBase = sbase + OFF_ASH + arow * 400 + akoff;

    // q fragments: ntg = 3h+j  -> byte (3h*8+g)*32 + t*8 + j*256
    // k fragments: ntg = 24+3h+j -> +6144;  vw: ntg=48 -> 12288 + 32g + 8t
    const char* bq0 = reinterpret_cast<const char*>(g_wpackB) +
                      (unsigned)((3 * h * 8 + g) * 32 + t * 8);
    const char* bv0 = reinterpret_cast<const char*>(g_wpackB) +
                      (unsigned)(12288 + g * 32 + t * 8);

    #pragma unroll
    for (int kt = 0; kt < 12; ++kt) {
      const char* bp = bq0 + kt * 12800;
      uint2 Bc[7];
      Bc[0] = *reinterpret_cast<const uint2*>(bp);
      Bc[1] = *reinterpret_cast<const uint2*>(bp + 256);
      Bc[2] = *reinterpret_cast<const uint2*>(bp + 512);
      Bc[3] = *reinterpret_cast<const uint2*>(bp + 6144);
      Bc[4] = *reinterpret_cast<const uint2*>(bp + 6400);
      Bc[5] = *reinterpret_cast<const uint2*>(bp + 6656);
      if (h < 4)
        Bc[6] = *reinterpret_cast<const uint2*>(bv0 + kt * 12800);
      #pragma unroll
      for (int mi = 0; mi < 4; ++mi) {
        unsigned Af[4];
        ldsm4(Af, aBase + mi * 6400 + kt * 32);
        #pragma unroll
        for (int j = 0; j < 3; ++j)
          mma_h(accq[mi][j], Af[0], Af[1], Af[2], Af[3], Bc[j].x, Bc[j].y);
        #pragma unroll
        for (int j = 0; j < 3; ++j)
          mma_h(acck[mi][j], Af[0], Af[1], Af[2], Af[3], Bc[3 + j].x,
                Bc[3 + j].y);
        if (h == mi)
          mma_h(accv, Af[0], Af[1], Af[2], Af[3], Bc[6].x, Bc[6].y);
      }
    }
  }

  // ---- q: (q+bq)*CEXP via HFMA2 (bias pre-scaled); k: plain bias add ----
  {
    const __half2 ce2 = __float2half2_rn(CEXP_);
    #pragma unroll
    for (int j = 0; j < 3; ++j) {
      __half2 bq =
          *reinterpret_cast<__half2*>(smu + BIAS2f + (3 * h + j) * 4 + t);
      __half2 bk =
          *reinterpret_cast<__half2*>(smu + BIAS2f + 96 + (3 * h + j) * 4 + t);
      #pragma unroll
      for (int mi = 0; mi < 4; ++mi) {
        #pragma unroll
        for (int c = 0; c < 2; ++c) {
          __half2 q2 =
              __hfma2(*reinterpret_cast<__half2*>(&accq[mi][j][c]), ce2, bq);
          accq[mi][j][c] = *reinterpret_cast<unsigned*>(&q2);
          __half2 k2 =
              __hadd2(*reinterpret_cast<__half2*>(&acck[mi][j][c]), bk);
          acck[mi][j][c] = *reinterpret_cast<unsigned*>(&k2);
        }
      }
    }
  }

  // ---- vw: warp h<4 writes all 8 head-cols for rows [h*16, h*16+16) ----
  if (h < 4) {
    __half2 c0 = *reinterpret_cast<__half2*>(&accv[0]);  // row g
    __half2 c1 = *reinterpret_cast<__half2*>(&accv[1]);  // row g+8
    int col0 = 2 * t, col1 = 2 * t + 1;
    float b0 = smf[BIASf + 384 + col0], b1 = smf[BIASf + 384 + col1];
    smf[VWf + col0 * 68 + h * 16 + g] = __low2float(c0) + b0;
    smf[VWf + col1 * 68 + h * 16 + g] = __high2float(c0) + b1;
    smf[VWf + col0 * 68 + h * 16 + 8 + g] = __low2float(c1) + b0;
    smf[VWf + col1 * 68 + h * 16 + 8 + g] = __high2float(c1) + b1;
  }
  __syncthreads();

  // preload vw pairs as f16x2 (one per kb)
  __half2 vv2[8];
  #pragma unroll
  for (int kb = 0; kb < 8; ++kb) {
    float2 vvk =
        *reinterpret_cast<const float2*>(smf + VWf + h * 68 + kb * 8 + t * 2);
    vv2[kb] = __floats2half2_rn(vvk.x, vvk.y);
  }

  // ---- attention: f16-acc logits (pre-scaled), f16x2 no-max softmax ----
  #pragma unroll
  for (int mt2 = 0; mt2 < 4; ++mt2) {
    unsigned acc[8][2];
    #pragma unroll
    for (int kb = 0; kb < 8; ++kb) acc[kb][0] = acc[kb][1] = 0u;
    #pragma unroll
    for (int kb = 0; kb < 8; ++kb) {
      mma_h(acc[kb], accq[mt2][0][0], accq[mt2][0][1], accq[mt2][1][0],
            accq[mt2][1][1], acck[kb >> 1][0][kb & 1],
            acck[kb >> 1][1][kb & 1]);
      mma8h(acc[kb], accq[mt2][2][0], accq[mt2][2][1],
            acck[kb >> 1][2][kb & 1]);
    }
    // row g -> acc[.][0], row g+8 -> acc[.][1]; halves = same-row columns
    __half2 sp2a = __float2half2_rn(0.f), sp2b = sp2a;
    __half2 sv2a = sp2a, sv2b = sp2a;
    #pragma unroll
    for (int kb = 0; kb < 8; ++kb) {
      unsigned p0u = h2exp2u(acc[kb][0]);
      unsigned p1u = h2exp2u(acc[kb][1]);
      __half2 p0 = *reinterpret_cast<__half2*>(&p0u);
      __half2 p1 = *reinterpret_cast<__half2*>(&p1u);
      sp2a = __hadd2(sp2a, p0);
      sp2b = __hadd2(sp2b, p1);
      sv2a = __hfma2(p0, vv2[kb], sv2a);
      sv2b = __hfma2(p1, vv2[kb], sv2b);
    }
    float2 fpa = __half22float2(sp2a), fpb = __half22float2(sp2b);
    float2 fva = __half22float2(sv2a), fvb = __half22float2(sv2b);
    float sp0 = fpa.x + fpa.y, sp1 = fpb.x + fpb.y;
    float sv0 = fva.x + fva.y, sv1 = fvb.x + fvb.y;
    sp0 += __shfl_xor_sync(0xffffffffu, sp0, 1);
    sv0 += __shfl_xor_sync(0xffffffffu, sv0, 1);
    sp1 += __shfl_xor_sync(0xffffffffu, sp1, 1);
    sv1 += __shfl_xor_sync(0xffffffffu, sv1, 1);
    sp0 += __shfl_xor_sync(0xffffffffu, sp0, 2);
    sv0 += __shfl_xor_sync(0xffffffffu, sv0, 2);
    sp1 += __shfl_xor_sync(0xffffffffu, sp1, 2);
    sv1 += __shfl_xor_sync(0xffffffffu, sv1, 2);
    if (t == 0) {
      smf[OUTPf + h * 64 + mt2 * 16 + g] = __fdividef(sv0, sp0);
      smf[OUTPf + h * 64 + mt2 * 16 + g + 8] = __fdividef(sv1, sp1);
    }
  }
  __syncthreads();

  // ---- final: sum 8 heads, sigmoid, store
  if (tid < 64) {
    float s = 0.f;
    #pragma unroll
    for (int hh = 0; hh < 8; ++hh) s += smf[OUTPf + hh * 64 + tid];
    float v = s + g_bpmean;
    float sig = __fdividef(1.f, 1.f + ex2a(v * -1.4426950408889634f));
    out[(size_t)bN * 65536 + (wy * 8 + (tid >> 3)) * 256 + wx * 8 +
        (tid & 7)] = sig;
  }
}

extern "C" void kernel_launch(void* const* d_in, const int* in_sizes, int n_in,
                              void* d_out, int out_size) {
  const float* x = (const float*)d_in[0];
  const float* gamma = (const float*)d_in[1];
  const float* beta = (const float*)d_in[2];
  const float* w_qkv = (const float*)d_in[3];
  const float* b_qkv = (const float*)d_in[4];
  const float* w_proj = (const float*)d_in[5];
  const float* b_proj = (const float*)d_in[6];
  float* out = (float*)d_out;

  cudaFuncSetAttribute(swin_reg_kernel,
                       cudaFuncAttributeMaxDynamicSharedMemorySize, SMEM_BYTES);

  pk_all<<<300, 256>>>(w_qkv, b_qkv, w_proj, b_proj);
  swin_reg_kernel<<<8192, 256, SMEM_BYTES>>>(x, gamma, beta, b_qkv, out);
}